// round 10
// baseline (speedup 1.0000x reference)
#include <cuda_runtime.h>

#define BB   4
#define NR   2
#define NREF 4
#define HH   320
#define WW   320
#define NPIX (HH*WW)

// Fully padded pair-image geometry:
//   pair entry physical (yp, jp), yp in [0, HH+3], jp in [0, WW+2]
//   logical row  ry = yp - 2   (rows -2,-1,HH,HH+1 are all-zero)
//   texels in entry: x0 = jp-2, x1 = jp-1  (zero outside [0,WW))
#define ROW2  (WW+3)           // 323 pairs per row
#define ROWS2 (HH+4)           // 324 rows
#define IMG2  (ROWS2*ROW2)     // entries per ref image

// Folded per-camera constants.
__device__ float g_A[BB*NR][12];    // invR@invK ; -invR@t
__device__ float g_P[BB*NREF][12];  // Kref@Rref ; Kref@tref

// Padded texel-pair image (11/11/10-bit packed RGB): 16*324*323*8B = 13.4 MB
__device__ uint2 g_img2[BB*NREF*IMG2];

__device__ __forceinline__ void inv3x3(const float m[9], float o[9]) {
    float a=m[0],b=m[1],c=m[2],d=m[3],e=m[4],f=m[5],g=m[6],h=m[7],i=m[8];
    float c00 =  (e*i - f*h);
    float c01 = -(d*i - f*g);
    float c02 =  (d*h - e*g);
    float det = a*c00 + b*c01 + c*c02;
    float id  = 1.0f/det;
    o[0]=c00*id;        o[1]=(c*h-b*i)*id;  o[2]=(b*f-c*e)*id;
    o[3]=c01*id;        o[4]=(a*i-c*g)*id;  o[5]=(c*d-a*f)*id;
    o[6]=c02*id;        o[7]=(b*g-a*h)*id;  o[8]=(a*e-b*d)*id;
}

__device__ __forceinline__ void precompute_mats(int t,
                                                const float* __restrict__ camK,
                                                const float* __restrict__ camW,
                                                const float* __restrict__ camKref,
                                                const float* __restrict__ camWref) {
    if (t < BB*NR) {
        float K[9], R[9], tv[3], invK[9], invR[9];
        #pragma unroll
        for (int i=0;i<9;i++) K[i]=camK[t*9+i];
        #pragma unroll
        for (int r=0;r<3;r++){
            #pragma unroll
            for(int c=0;c<3;c++) R[r*3+c]=camW[t*12+r*4+c];
            tv[r]=camW[t*12+r*4+3];
        }
        inv3x3(K, invK);
        inv3x3(R, invR);
        #pragma unroll
        for (int r=0;r<3;r++) {
            #pragma unroll
            for (int c=0;c<3;c++) {
                float s=0.f;
                #pragma unroll
                for (int k=0;k<3;k++) s += invR[r*3+k]*invK[k*3+c];
                g_A[t][r*3+c]=s;
            }
            float s=0.f;
            #pragma unroll
            for (int k=0;k<3;k++) s += invR[r*3+k]*tv[k];
            g_A[t][9+r] = -s;
        }
    }
    if (t < BB*NREF) {
        float K[9], R[9], tv[3];
        #pragma unroll
        for (int i=0;i<9;i++) K[i]=camKref[t*9+i];
        #pragma unroll
        for (int r=0;r<3;r++){
            #pragma unroll
            for(int c=0;c<3;c++) R[r*3+c]=camWref[t*12+r*4+c];
            tv[r]=camWref[t*12+r*4+3];
        }
        #pragma unroll
        for (int r=0;r<3;r++) {
            #pragma unroll
            for (int c=0;c<3;c++) {
                float s=0.f;
                #pragma unroll
                for (int k=0;k<3;k++) s += K[r*3+k]*R[k*3+c];
                g_P[t][r*3+c]=s;
            }
            float s=0.f;
            #pragma unroll
            for (int k=0;k<3;k++) s += K[r*3+k]*tv[k];
            g_P[t][9+r]=s;
        }
    }
}

__device__ __forceinline__ unsigned pack_tex(const float* __restrict__ src, int pix) {
    float r = src[pix];
    float g = src[pix + NPIX];
    float b = src[pix + 2*NPIX];
    unsigned ri = __float2uint_rn(r * 2047.f);
    unsigned gi = __float2uint_rn(g * 2047.f);
    unsigned bi = __float2uint_rn(b * 1023.f);
    return ri | (gi << 11) | (bi << 22);
}

// Planar float (rf,3,H,W) -> fully padded texel-pair image.
// Block 0 additionally folds the camera matrices.
__global__ __launch_bounds__(256)
void repack_kernel(const float* __restrict__ image_ref,
                   const float* __restrict__ camK,
                   const float* __restrict__ camW,
                   const float* __restrict__ camKref,
                   const float* __restrict__ camWref) {
    if (blockIdx.x == 0 && threadIdx.x < 32)
        precompute_mats(threadIdx.x, camK, camW, camKref, camWref);

    int i = blockIdx.x*256 + threadIdx.x;      // over BB*NREF*IMG2
    if (i >= BB*NREF*IMG2) return;
    int rf  = i / IMG2;
    int rem = i - rf*IMG2;
    int yp  = rem / ROW2;
    int jp  = rem - yp*ROW2;

    int ry = yp - 2;                           // logical row
    int x0 = jp - 2;                           // texel x of .x
    int x1 = jp - 1;                           // texel x of .y

    uint2 v = make_uint2(0u, 0u);
    if (ry >= 0 && ry < HH) {
        const float* src = image_ref + (size_t)rf*3*NPIX;
        if (x0 >= 0 && x0 < WW) v.x = pack_tex(src, ry*WW + x0);
        if (x1 >= 0 && x1 < WW) v.y = pack_tex(src, ry*WW + x1);
    }
    g_img2[i] = v;
}

// Mantissa-OR decode: f = 1 + field * 2^-k, no I2F.
__device__ __forceinline__ void dec_acc(unsigned t, float w,
                                        float& a0, float& a1, float& a2) {
    float fr = __uint_as_float(((t << 12) & 0x7FF000u) | 0x3F800000u); // 1+r*2^-11
    float fg = __uint_as_float(((t << 1)  & 0x7FF000u) | 0x3F800000u); // 1+g*2^-11
    float fb = __uint_as_float(((t >> 9)  & 0x7FE000u) | 0x3F800000u); // 1+b*2^-10
    a0 = fmaf(w, fr, a0);
    a1 = fmaf(w, fg, a1);
    a2 = fmaf(w, fb, a2);
}

// 2 px/thread; branch-free; 3-phase staging: all 8 addresses -> all 16 LDG.64
// -> all decodes. Masked pixels read entry 0 (zero padding, broadcast).
__global__ __launch_bounds__(256, 4)
void render_kernel(const float* __restrict__ depth,
                   const float* __restrict__ background,
                   float* __restrict__ out) {
    int tx  = threadIdx.x;                 // 0..31
    int ty  = threadIdx.y;                 // 0..7
    int x0  = blockIdx.x*64 + tx*2;
    int y   = blockIdx.y*8  + ty;
    int cam = blockIdx.z;                  // b*NR + nr
    int b   = cam >> 1;                    // NR == 2

    int pix = y*WW + x0;
    float2 d2 = *reinterpret_cast<const float2*>(depth + cam*NPIX + pix);
    size_t obase = (size_t)cam*3*NPIX + pix;

    float2 bg0 = *reinterpret_cast<const float2*>(background + obase);
    float2 bg1 = *reinterpret_cast<const float2*>(background + obase + NPIX);
    float2 bg2 = *reinterpret_cast<const float2*>(background + obase + 2*NPIX);

    bool m[2] = { d2.x > 0.f, d2.y > 0.f };
    float dv[2] = { d2.x, d2.y };

    const float* Ac = g_A[cam];
    float pxv[2], pyv[2], pzv[2];
    #pragma unroll
    for (int p=0; p<2; p++) {
        float fx = (float)(x0 + p), fy = (float)y;
        float hx = Ac[0]*fx + Ac[1]*fy + Ac[2];
        float hy = Ac[3]*fx + Ac[4]*fy + Ac[5];
        float hz = Ac[6]*fx + Ac[7]*fy + Ac[8];
        pxv[p] = -dv[p]*hx + Ac[9];
        pyv[p] = -dv[p]*hy + Ac[10];
        pzv[p] = -dv[p]*hz + Ac[11];
    }

    // ---- Phase 1: all 8 fetch sites -> idx, wx, wy -------------------------
    int   idxA[NREF*2];
    float wxA[NREF*2], wyA[NREF*2];
    #pragma unroll
    for (int r=0; r<NREF; r++) {
        const float* P = g_P[b*NREF + r];
        float P0=P[0],P1=P[1],P2=P[2],P3=P[3],P4=P[4],P5=P[5];
        float P6=P[6],P7=P[7],P8=P[8],P9=P[9],P10=P[10],P11=P[11];
        #pragma unroll
        for (int p=0; p<2; p++) {
            int k = r*2 + p;
            float qx = P0*pxv[p] + P1*pyv[p] + P2*pzv[p] + P9;
            float qy = P3*pxv[p] + P4*pyv[p] + P5*pzv[p] + P10;
            float qz = P6*pxv[p] + P7*pyv[p] + P8*pzv[p] + P11;
            float inv = __fdividef(1.f, qz);
            float u = qx*inv;
            float v = qy*inv;
            float x0f = floorf(u), y0f = floorf(v);
            wxA[k] = u - x0f;
            wyA[k] = v - y0f;
            int jp = min(max(__float2int_rz(x0f) + 2, 0), WW+2);
            int yp = min(max(__float2int_rz(y0f), -2), HH) + 2;
            // masked pixels: broadcast-read entry 0 (zero padding)
            idxA[k] = m[p] ? (yp*ROW2 + jp) : 0;
        }
    }

    // ---- Phase 2: issue all 16 LDG.64 back-to-back -------------------------
    uint2 T0[NREF*2], T1[NREF*2];
    #pragma unroll
    for (int k=0; k<NREF*2; k++) {
        const uint2* fm = g_img2 + (size_t)(b*NREF + (k>>1))*IMG2;
        T0[k] = __ldg(fm + idxA[k]);
        T1[k] = __ldg(fm + idxA[k] + ROW2);
    }

    // ---- Phase 3: decode + accumulate --------------------------------------
    float acc[2][3] = {{0.f,0.f,0.f},{0.f,0.f,0.f}};
    #pragma unroll
    for (int k=0; k<NREF*2; k++) {
        int p = k & 1;
        float wx = wxA[k], wy = wyA[k];
        float wxl = 1.f - wx, wyt = 1.f - wy;
        float w00 = wxl*wyt, w01 = wx*wyt;
        float w10 = wxl*wy,  w11 = wx*wy;      // sums to 1
        dec_acc(T0[k].x, w00, acc[p][0], acc[p][1], acc[p][2]);
        dec_acc(T0[k].y, w01, acc[p][0], acc[p][1], acc[p][2]);
        dec_acc(T1[k].x, w10, acc[p][0], acc[p][1], acc[p][2]);
        dec_acc(T1[k].y, w11, acc[p][0], acc[p][1], acc[p][2]);
    }

    // acc = NREF + sum(w * field * 2^-k)  ->  out = (acc - 4) * scale
    const float sRG = 0.25f * 2048.f / 2047.f;
    const float sB  = 0.25f * 1024.f / 1023.f;
    const float bRG = -4.f * sRG;
    const float bB  = -4.f * sB;

    float2 o0 = { m[0] ? fmaf(acc[0][0], sRG, bRG) : bg0.x,
                  m[1] ? fmaf(acc[1][0], sRG, bRG) : bg0.y };
    float2 o1 = { m[0] ? fmaf(acc[0][1], sRG, bRG) : bg1.x,
                  m[1] ? fmaf(acc[1][1], sRG, bRG) : bg1.y };
    float2 o2 = { m[0] ? fmaf(acc[0][2], sB,  bB ) : bg2.x,
                  m[1] ? fmaf(acc[1][2], sB,  bB ) : bg2.y };

    *reinterpret_cast<float2*>(out + obase)          = o0;
    *reinterpret_cast<float2*>(out + obase + NPIX)   = o1;
    *reinterpret_cast<float2*>(out + obase + 2*NPIX) = o2;
}

extern "C" void kernel_launch(void* const* d_in, const int* in_sizes, int n_in,
                              void* d_out, int out_size) {
    // metadata order: depth, cam_K, cam_W, image_ref, background,
    //                 cube_diagonal, cam_K_ref, cam_W_ref
    const float* depth      = (const float*)d_in[0];
    const float* cam_K      = (const float*)d_in[1];
    const float* cam_W      = (const float*)d_in[2];
    const float* image_ref  = (const float*)d_in[3];
    const float* background = (const float*)d_in[4];
    // d_in[5] = cube_diagonal: algebraically cancels -> unused
    const float* cam_K_ref  = (const float*)d_in[6];
    const float* cam_W_ref  = (const float*)d_in[7];
    float* out = (float*)d_out;

    int n_entries = BB*NREF*IMG2;
    repack_kernel<<<(n_entries + 255)/256, 256>>>(image_ref, cam_K, cam_W,
                                                  cam_K_ref, cam_W_ref);

    dim3 block(32, 8, 1);
    dim3 grid(WW/64, HH/8, BB*NR);
    render_kernel<<<grid, block>>>(depth, background, out);
}